// round 3
// baseline (speedup 1.0000x reference)
#include <cuda_runtime.h>
#include <math.h>

#define N_NODES 50000
#define E0      800000
#define NE      850000   // with self loops
#define F_IN    1433
#define H1      512
#define H2      256
#define NC      7

// ---------------- scratch (device globals; no allocations) ----------------
__device__ float g_buf1[(size_t)N_NODES * 512];   // GEMM output h
__device__ float g_buf2[(size_t)N_NODES * 512];   // aggregated output / next input
__device__ float g_ss[N_NODES];
__device__ float g_sd[N_NODES];
__device__ float g_m[N_NODES];
__device__ float g_den[N_NODES];
__device__ float g_ee[NE];
__device__ int   g_src[NE];
__device__ int   g_dst[NE];
__device__ float g_c[(size_t)N_NODES * NC];       // layer-3 aggregate
__device__ int   g_is64;

// ---------------- helpers ----------------
__device__ __forceinline__ void atomicMaxF(float* addr, float v) {
    if (v >= 0.0f) atomicMax((int*)addr, __float_as_int(v));
    else           atomicMin((unsigned int*)addr, __float_as_uint(v));
}

// ---------------- kernels ----------------
// Detect whether edge_index buffer is int64 or int32: for int64 values < 2^31,
// every odd 32-bit word is 0; for random int32 node ids, odd words are nonzero.
__global__ void detect_kernel(const unsigned int* __restrict__ w) {
    __shared__ int nz;
    if (threadIdx.x == 0) nz = 0;
    __syncthreads();
    if (w[threadIdx.x * 2 + 1] != 0u) atomicOr(&nz, 1);
    __syncthreads();
    if (threadIdx.x == 0) g_is64 = (nz == 0);
}

__global__ void prep_edges_kernel(const void* __restrict__ ei) {
    int i = blockIdx.x * blockDim.x + threadIdx.x;
    if (i >= NE) return;
    int s, d;
    if (i < E0) {
        if (g_is64) {
            const long long* e = (const long long*)ei;
            s = (int)e[i]; d = (int)e[E0 + i];
        } else {
            const int* e = (const int*)ei;
            s = e[i]; d = e[E0 + i];
        }
    } else {
        s = d = i - E0;
    }
    // defensive clamp: wrong decode shows up as rel_err, not a crash
    s = min(max(s, 0), N_NODES - 1);
    d = min(max(d, 0), N_NODES - 1);
    g_src[i] = s;
    g_dst[i] = d;
}

__global__ void zero_kernel(float* __restrict__ p, size_t n) {
    size_t i = (size_t)blockIdx.x * blockDim.x + threadIdx.x;
    size_t stride = (size_t)gridDim.x * blockDim.x;
    for (; i < n; i += stride) p[i] = 0.0f;
}

// 64x64 tile, 256 threads, 4x4 per thread, K-chunks of 16. fp32.
__global__ void gemm_kernel(const float* __restrict__ A, const float* __restrict__ B,
                            float* __restrict__ C, int M, int K, int N) {
    __shared__ float As[16][68];   // padded: avoids 16-way store conflicts
    __shared__ float Bs[16][64];
    int tid = threadIdx.x;
    int tx = tid & 15, ty = tid >> 4;
    int m0 = blockIdx.y * 64, n0 = blockIdx.x * 64;

    float acc00=0,acc01=0,acc02=0,acc03=0;
    float acc10=0,acc11=0,acc12=0,acc13=0;
    float acc20=0,acc21=0,acc22=0,acc23=0;
    float acc30=0,acc31=0,acc32=0,acc33=0;

    for (int k0 = 0; k0 < K; k0 += 16) {
        #pragma unroll
        for (int i = 0; i < 4; i++) {
            int m  = (tid >> 4) + i * 16;
            int kk = tid & 15;
            float v = 0.0f;
            if (m0 + m < M && k0 + kk < K)
                v = A[(size_t)(m0 + m) * K + (k0 + kk)];
            As[kk][m] = v;
        }
        #pragma unroll
        for (int i = 0; i < 4; i++) {
            int kk = (tid >> 6) + i * 4;
            int n  = tid & 63;
            float v = 0.0f;
            if (k0 + kk < K)
                v = B[(size_t)(k0 + kk) * N + (n0 + n)];
            Bs[kk][n] = v;
        }
        __syncthreads();
        #pragma unroll
        for (int kk = 0; kk < 16; kk++) {
            float4 a = *(const float4*)&As[kk][ty * 4];
            float4 b = *(const float4*)&Bs[kk][tx * 4];
            acc00 += a.x*b.x; acc01 += a.x*b.y; acc02 += a.x*b.z; acc03 += a.x*b.w;
            acc10 += a.y*b.x; acc11 += a.y*b.y; acc12 += a.y*b.z; acc13 += a.y*b.w;
            acc20 += a.z*b.x; acc21 += a.z*b.y; acc22 += a.z*b.z; acc23 += a.z*b.w;
            acc30 += a.w*b.x; acc31 += a.w*b.y; acc32 += a.w*b.z; acc33 += a.w*b.w;
        }
        __syncthreads();
    }

    int mbase = m0 + ty * 4;
    int nbase = n0 + tx * 4;   // N is a multiple of 64 here
    if (mbase + 0 < M) *(float4*)&C[(size_t)(mbase+0)*N + nbase] = make_float4(acc00,acc01,acc02,acc03);
    if (mbase + 1 < M) *(float4*)&C[(size_t)(mbase+1)*N + nbase] = make_float4(acc10,acc11,acc12,acc13);
    if (mbase + 2 < M) *(float4*)&C[(size_t)(mbase+2)*N + nbase] = make_float4(acc20,acc21,acc22,acc23);
    if (mbase + 3 < M) *(float4*)&C[(size_t)(mbase+3)*N + nbase] = make_float4(acc30,acc31,acc32,acc33);
}

// per-node attention scores: ss = h . a_src, sd = h . a_dst; also init m/den
__global__ void s_kernel(const float* __restrict__ h, const float* __restrict__ a_s,
                         const float* __restrict__ a_d, int F) {
    int node = blockIdx.x * (blockDim.x >> 5) + (threadIdx.x >> 5);
    int lane = threadIdx.x & 31;
    if (node >= N_NODES) return;
    const float* hr = h + (size_t)node * F;
    float vs = 0.0f, vd = 0.0f;
    for (int f = lane; f < F; f += 32) {
        float x = hr[f];
        vs += x * a_s[f];
        vd += x * a_d[f];
    }
    #pragma unroll
    for (int o = 16; o > 0; o >>= 1) {
        vs += __shfl_down_sync(0xffffffffu, vs, o);
        vd += __shfl_down_sync(0xffffffffu, vd, o);
    }
    if (lane == 0) {
        g_ss[node] = vs;
        g_sd[node] = vd;
        g_m[node]  = -INFINITY;
        g_den[node] = 0.0f;
    }
}

__global__ void edge_max_kernel() {
    int e = blockIdx.x * blockDim.x + threadIdx.x;
    if (e >= NE) return;
    int s = g_src[e], d = g_dst[e];
    float v = g_ss[s] + g_sd[d];
    v = v > 0.0f ? v : 0.2f * v;      // leaky relu
    g_ee[e] = v;
    atomicMaxF(&g_m[d], v);
}

__global__ void edge_exp_kernel() {
    int e = blockIdx.x * blockDim.x + threadIdx.x;
    if (e >= NE) return;
    int d = g_dst[e];
    float ee = __expf(g_ee[e] - g_m[d]);
    g_ee[e] = ee;
    atomicAdd(&g_den[d], ee);
}

// warp per edge; F multiple of 4
__global__ void edge_agg_kernel(const float* __restrict__ h, float* __restrict__ out, int F) {
    int e = blockIdx.x * (blockDim.x >> 5) + (threadIdx.x >> 5);
    if (e >= NE) return;
    int lane = threadIdx.x & 31;
    int s = g_src[e], d = g_dst[e];
    float w = g_ee[e] / g_den[d];
    const float4* hs = (const float4*)(h + (size_t)s * F);
    float* o = out + (size_t)d * F;
    int F4 = F >> 2;
    for (int f = lane; f < F4; f += 32) {
        float4 v = hs[f];
        atomicAdd(o + f*4 + 0, w * v.x);
        atomicAdd(o + f*4 + 1, w * v.y);
        atomicAdd(o + f*4 + 2, w * v.z);
        atomicAdd(o + f*4 + 3, w * v.w);
    }
}

__global__ void bias_relu_kernel(float* __restrict__ p, const float* __restrict__ b,
                                 int F, int do_relu) {
    size_t i = (size_t)blockIdx.x * blockDim.x + threadIdx.x;
    size_t n = (size_t)N_NODES * F;
    if (i >= n) return;
    int f = (int)(i % F);
    float x = p[i] + b[f];
    p[i] = do_relu ? fmaxf(x, 0.0f) : x;
}

// layer-3 skinny GEMM: [N,256] @ [256,7]
__global__ void gemm3_kernel(const float* __restrict__ A, const float* __restrict__ W,
                             float* __restrict__ C) {
    int i = blockIdx.x * blockDim.x + threadIdx.x;
    if (i >= N_NODES) return;
    const float* a = A + (size_t)i * H2;
    float acc[NC] = {0,0,0,0,0,0,0};
    for (int k = 0; k < H2; k++) {
        float av = a[k];
        const float* wr = W + k * NC;
        #pragma unroll
        for (int c = 0; c < NC; c++) acc[c] += av * wr[c];
    }
    #pragma unroll
    for (int c = 0; c < NC; c++) C[(size_t)i * NC + c] = acc[c];
}

// scalar aggregation for F=7
__global__ void edge_agg7_kernel(const float* __restrict__ h, float* __restrict__ out) {
    int e = blockIdx.x * blockDim.x + threadIdx.x;
    if (e >= NE) return;
    int s = g_src[e], d = g_dst[e];
    float w = g_ee[e] / g_den[d];
    const float* hs = h + (size_t)s * NC;
    float* o = out + (size_t)d * NC;
    #pragma unroll
    for (int c = 0; c < NC; c++) atomicAdd(o + c, w * hs[c]);
}

// add bias + log_softmax over 7 classes -> final output
__global__ void final_kernel(const float* __restrict__ agg, const float* __restrict__ b,
                             float* __restrict__ out) {
    int i = blockIdx.x * blockDim.x + threadIdx.x;
    if (i >= N_NODES) return;
    float z[NC];
    float mx = -INFINITY;
    #pragma unroll
    for (int c = 0; c < NC; c++) {
        z[c] = agg[(size_t)i * NC + c] + b[c];
        mx = fmaxf(mx, z[c]);
    }
    float ssum = 0.0f;
    #pragma unroll
    for (int c = 0; c < NC; c++) ssum += __expf(z[c] - mx);
    float l = logf(ssum);
    #pragma unroll
    for (int c = 0; c < NC; c++) out[(size_t)i * NC + c] = z[c] - mx - l;
}

// ---------------- launcher ----------------
extern "C" void kernel_launch(void* const* d_in, const int* in_sizes, int n_in,
                              void* d_out, int out_size) {
    const float* x   = (const float*)d_in[0];
    const void*  ei  = d_in[1];
    const float* W1  = (const float*)d_in[2];
    const float* as1 = (const float*)d_in[3];
    const float* ad1 = (const float*)d_in[4];
    const float* b1  = (const float*)d_in[5];
    const float* W2  = (const float*)d_in[6];
    const float* as2 = (const float*)d_in[7];
    const float* ad2 = (const float*)d_in[8];
    const float* b2  = (const float*)d_in[9];
    const float* W3  = (const float*)d_in[10];
    const float* as3 = (const float*)d_in[11];
    const float* ad3 = (const float*)d_in[12];
    const float* b3  = (const float*)d_in[13];
    float* out = (float*)d_out;

    float *buf1, *buf2, *cbuf;
    cudaGetSymbolAddress((void**)&buf1, g_buf1);
    cudaGetSymbolAddress((void**)&buf2, g_buf2);
    cudaGetSymbolAddress((void**)&cbuf, g_c);

    const int BT = 256;
    const int edge_blocks      = (NE + BT - 1) / BT;
    const int edge_warp_blocks = (NE + (BT/32) - 1) / (BT/32);
    const int node_warp_blocks = (N_NODES + (BT/32) - 1) / (BT/32);
    const int node_blocks      = (N_NODES + BT - 1) / BT;

    detect_kernel<<<1, 128>>>((const unsigned int*)ei);
    prep_edges_kernel<<<edge_blocks, BT>>>(ei);

    // ---------------- layer 1: F_IN -> H1 ----------------
    gemm_kernel<<<dim3(H1/64, (N_NODES + 63)/64), BT>>>(x, W1, buf1, N_NODES, F_IN, H1);
    s_kernel<<<node_warp_blocks, BT>>>(buf1, as1, ad1, H1);
    zero_kernel<<<2048, BT>>>(buf2, (size_t)N_NODES * H1);
    edge_max_kernel<<<edge_blocks, BT>>>();
    edge_exp_kernel<<<edge_blocks, BT>>>();
    edge_agg_kernel<<<edge_warp_blocks, BT>>>(buf1, buf2, H1);
    bias_relu_kernel<<<(int)(((size_t)N_NODES*H1 + BT - 1)/BT), BT>>>(buf2, b1, H1, 1);

    // ---------------- layer 2: H1 -> H2 ----------------
    gemm_kernel<<<dim3(H2/64, (N_NODES + 63)/64), BT>>>(buf2, W2, buf1, N_NODES, H1, H2);
    s_kernel<<<node_warp_blocks, BT>>>(buf1, as2, ad2, H2);
    zero_kernel<<<2048, BT>>>(buf2, (size_t)N_NODES * H2);
    edge_max_kernel<<<edge_blocks, BT>>>();
    edge_exp_kernel<<<edge_blocks, BT>>>();
    edge_agg_kernel<<<edge_warp_blocks, BT>>>(buf1, buf2, H2);
    bias_relu_kernel<<<(int)(((size_t)N_NODES*H2 + BT - 1)/BT), BT>>>(buf2, b2, H2, 1);

    // ---------------- layer 3: H2 -> NC ----------------
    gemm3_kernel<<<node_blocks, BT>>>(buf2, W3, buf1);
    s_kernel<<<node_warp_blocks, BT>>>(buf1, as3, ad3, NC);
    zero_kernel<<<512, BT>>>(cbuf, (size_t)N_NODES * NC);
    edge_max_kernel<<<edge_blocks, BT>>>();
    edge_exp_kernel<<<edge_blocks, BT>>>();
    edge_agg7_kernel<<<edge_blocks, BT>>>(buf1, cbuf);
    final_kernel<<<node_blocks, BT>>>(cbuf, b3, out);
}

// round 5
// speedup vs baseline: 1.4220x; 1.4220x over previous
#include <cuda_runtime.h>
#include <cuda_bf16.h>
#include <math.h>
#include <stdint.h>

#define N_NODES 50000
#define MPAD    50048   // 391 * 128
#define E0      800000
#define NE      850000
#define F_IN    1433
#define K1PAD   1472    // 46 * 32
#define H1      512
#define H2      256
#define NC      7

// ==================== scratch (device globals) ====================
__device__ __nv_bfloat16 g_Ahi[(size_t)MPAD * K1PAD];
__device__ __nv_bfloat16 g_Alo[(size_t)MPAD * K1PAD];
__device__ __nv_bfloat16 g_Bhi[(size_t)H1 * K1PAD];
__device__ __nv_bfloat16 g_Blo[(size_t)H1 * K1PAD];
__device__ float g_buf1[(size_t)MPAD * H1];
__device__ float g_buf2[(size_t)MPAD * H1];
__device__ float g_ss[N_NODES];
__device__ float g_sd[N_NODES];
__device__ float g_m[N_NODES];
__device__ float g_den[N_NODES];
__device__ float g_ee[NE];
__device__ int   g_src[NE];
__device__ int   g_dst[NE];
__device__ float g_c[(size_t)N_NODES * NC];
__device__ int   g_is64;

// ==================== PTX helpers (base-arch only!) ====================
__device__ __forceinline__ uint32_t smem_u32(const void* p) {
    uint32_t a;
    asm("{ .reg .u64 t; cvta.to.shared.u64 t, %1; cvt.u32.u64 %0, t; }" : "=r"(a) : "l"(p));
    return a;
}
__device__ __forceinline__ void cp16(uint32_t dst, const void* src) {
    asm volatile("cp.async.cg.shared.global [%0], [%1], 16;" :: "r"(dst), "l"(src));
}
__device__ __forceinline__ void ldm_x4(uint32_t& r0, uint32_t& r1, uint32_t& r2, uint32_t& r3,
                                       uint32_t addr) {
    asm volatile("ldmatrix.sync.aligned.m8n8.x4.shared.b16 {%0,%1,%2,%3}, [%4];"
                 : "=r"(r0), "=r"(r1), "=r"(r2), "=r"(r3) : "r"(addr));
}
__device__ __forceinline__ void mma_bf16(float* c, const uint32_t* a, const uint32_t* b) {
    asm volatile("mma.sync.aligned.m16n8k16.row.col.f32.bf16.bf16.f32 "
                 "{%0,%1,%2,%3}, {%4,%5,%6,%7}, {%8,%9}, {%0,%1,%2,%3};"
                 : "+f"(c[0]), "+f"(c[1]), "+f"(c[2]), "+f"(c[3])
                 : "r"(a[0]), "r"(a[1]), "r"(a[2]), "r"(a[3]), "r"(b[0]), "r"(b[1]));
}

__device__ __forceinline__ void atomicMaxF(float* addr, float v) {
    if (v >= 0.0f) atomicMax((int*)addr, __float_as_int(v));
    else           atomicMin((unsigned int*)addr, __float_as_uint(v));
}

// ==================== graph / edge kernels ====================
__global__ void detect_kernel(const unsigned int* __restrict__ w) {
    __shared__ int nz;
    if (threadIdx.x == 0) nz = 0;
    __syncthreads();
    if (w[threadIdx.x * 2 + 1] != 0u) atomicOr(&nz, 1);
    __syncthreads();
    if (threadIdx.x == 0) g_is64 = (nz == 0);
}

__global__ void prep_edges_kernel(const void* __restrict__ ei) {
    int i = blockIdx.x * blockDim.x + threadIdx.x;
    if (i >= NE) return;
    int s, d;
    if (i < E0) {
        if (g_is64) {
            const long long* e = (const long long*)ei;
            s = (int)e[i]; d = (int)e[E0 + i];
        } else {
            const int* e = (const int*)ei;
            s = e[i]; d = e[E0 + i];
        }
    } else {
        s = d = i - E0;
    }
    s = min(max(s, 0), N_NODES - 1);
    d = min(max(d, 0), N_NODES - 1);
    g_src[i] = s;
    g_dst[i] = d;
}

__global__ void zero_kernel(float* __restrict__ p, size_t n) {
    size_t i = (size_t)blockIdx.x * blockDim.x + threadIdx.x;
    size_t stride = (size_t)gridDim.x * blockDim.x;
    for (; i < n; i += stride) p[i] = 0.0f;
}

// ==================== precision-split conversion ====================
__global__ void split_A_kernel(const float* __restrict__ A, int M, int K, int Kpad,
                               __nv_bfloat16* __restrict__ hi, __nv_bfloat16* __restrict__ lo) {
    size_t total = (size_t)MPAD * Kpad;
    size_t i = (size_t)blockIdx.x * blockDim.x + threadIdx.x;
    size_t stride = (size_t)gridDim.x * blockDim.x;
    for (; i < total; i += stride) {
        int r = (int)(i / Kpad), c = (int)(i % Kpad);
        float v = (r < M && c < K) ? A[(size_t)r * K + c] : 0.0f;
        __nv_bfloat16 h = __float2bfloat16(v);
        hi[i] = h;
        lo[i] = __float2bfloat16(v - __bfloat162float(h));
    }
}

__global__ void split_Wt_kernel(const float* __restrict__ W, int K, int N, int Kpad,
                                __nv_bfloat16* __restrict__ hi, __nv_bfloat16* __restrict__ lo) {
    size_t total = (size_t)N * Kpad;
    size_t i = (size_t)blockIdx.x * blockDim.x + threadIdx.x;
    size_t stride = (size_t)gridDim.x * blockDim.x;
    for (; i < total; i += stride) {
        int n = (int)(i / Kpad), k = (int)(i % Kpad);
        float v = (k < K) ? W[(size_t)k * N + n] : 0.0f;
        __nv_bfloat16 h = __float2bfloat16(v);
        hi[i] = h;
        lo[i] = __float2bfloat16(v - __bfloat162float(h));
    }
}

// ==================== mma.sync bf16x3 GEMM ====================
// C[MPAD,Nc] = A(hi+lo)[MPAD,Kpad] x (B(hi+lo)[Nc,Kpad])^T  (B rows are K-major)
// CTA tile 128x128, 8 warps (4x2), warp tile 32x64, K-chunk 32, double-buffered cp.async.
// smem pitch: 40 bf16 = 80 B per row (conflict-free for cp.async stores + ldmatrix).
#define KC        32
#define SPITCH    80            // bytes per smem row
#define ARR_BYTES (128 * SPITCH)    // 10240
#define STG_BYTES (4 * ARR_BYTES)   // 40960
#define OFF_AHI   0
#define OFF_ALO   ARR_BYTES
#define OFF_BHI   (2 * ARR_BYTES)
#define OFF_BLO   (3 * ARR_BYTES)
#define SMEM_DYN  (2 * STG_BYTES)   // 81920

__global__ void __launch_bounds__(256)
gemm_tc_kernel(const __nv_bfloat16* __restrict__ Ahi, const __nv_bfloat16* __restrict__ Alo,
               const __nv_bfloat16* __restrict__ Bhi, const __nv_bfloat16* __restrict__ Blo,
               float* __restrict__ C, int Kpad, int Nc) {
    extern __shared__ char smem[];
    const uint32_t sb = smem_u32(smem);
    const int tid = threadIdx.x;
    const int wid = tid >> 5, lane = tid & 31;
    const int warp_m = wid & 3, warp_n = wid >> 2;
    const int m0 = blockIdx.y * 128;
    const int n0 = blockIdx.x * 128;
    const int nchunks = Kpad / KC;

    // ---- per-thread load mapping: 2 tasks x (4 arrays) per chunk ----
    const int row0 = tid >> 2, seg = tid & 3;           // task 0: rows 0..63
    const int row1 = row0 + 64;                          // task 1: rows 64..127
    const uint32_t s0 = (uint32_t)row0 * SPITCH + seg * 16;
    const uint32_t s1 = (uint32_t)row1 * SPITCH + seg * 16;
    const size_t gA0 = (size_t)(m0 + row0) * Kpad + seg * 8;
    const size_t gA1 = (size_t)(m0 + row1) * Kpad + seg * 8;
    const size_t gB0 = (size_t)(n0 + row0) * Kpad + seg * 8;
    const size_t gB1 = (size_t)(n0 + row1) * Kpad + seg * 8;

    // ---- ldmatrix lane addressing ----
    const int lr = lane & 7, g = lane >> 3;
    // A tile (m16 x k16): matrices [m0-7,k0-7],[m8-15,k0-7],[m0-7,k8-15],[m8-15,k8-15]
    const uint32_t offA = (uint32_t)(warp_m * 32 + lr + (g & 1) * 8) * SPITCH + (g >> 1) * 16;
    // B tile-pair (n16 x k16): [n0-7,k0-7],[n0-7,k8-15],[n8-15,k0-7],[n8-15,k8-15]
    const uint32_t offB = (uint32_t)(warp_n * 64 + lr + (g >> 1) * 8) * SPITCH + (g & 1) * 16;

    float acc[2][8][4];
    #pragma unroll
    for (int mi = 0; mi < 2; mi++)
        #pragma unroll
        for (int ni = 0; ni < 8; ni++)
            #pragma unroll
            for (int q = 0; q < 4; q++) acc[mi][ni][q] = 0.0f;

    // ---- prologue: stage 0 ----
    {
        const uint32_t d = sb;
        cp16(d + OFF_AHI + s0, Ahi + gA0); cp16(d + OFF_AHI + s1, Ahi + gA1);
        cp16(d + OFF_ALO + s0, Alo + gA0); cp16(d + OFF_ALO + s1, Alo + gA1);
        cp16(d + OFF_BHI + s0, Bhi + gB0); cp16(d + OFF_BHI + s1, Bhi + gB1);
        cp16(d + OFF_BLO + s0, Blo + gB0); cp16(d + OFF_BLO + s1, Blo + gB1);
        asm volatile("cp.async.commit_group;");
    }

    for (int c = 0; c < nchunks; c++) {
        if (c + 1 < nchunks) {
            const uint32_t d = sb + ((c + 1) & 1) * STG_BYTES;
            const size_t ko = (size_t)(c + 1) * KC;
            cp16(d + OFF_AHI + s0, Ahi + gA0 + ko); cp16(d + OFF_AHI + s1, Ahi + gA1 + ko);
            cp16(d + OFF_ALO + s0, Alo + gA0 + ko); cp16(d + OFF_ALO + s1, Alo + gA1 + ko);
            cp16(d + OFF_BHI + s0, Bhi + gB0 + ko); cp16(d + OFF_BHI + s1, Bhi + gB1 + ko);
            cp16(d + OFF_BLO + s0, Blo + gB0 + ko); cp16(d + OFF_BLO + s1, Blo + gB1 + ko);
            asm volatile("cp.async.commit_group;");
            asm volatile("cp.async.wait_group 1;");
        } else {
            asm volatile("cp.async.wait_group 0;");
        }
        __syncthreads();

        const uint32_t base = sb + (c & 1) * STG_BYTES;
        #pragma unroll
        for (int ks = 0; ks < 2; ks++) {           // two k16 steps per chunk
            const uint32_t kadd = ks * 32;         // 16 bf16 = 32 bytes
            uint32_t ahi[2][4], alo[2][4], bhi[8][2], blo[8][2];
            #pragma unroll
            for (int mt = 0; mt < 2; mt++) {
                ldm_x4(ahi[mt][0], ahi[mt][1], ahi[mt][2], ahi[mt][3],
                       base + OFF_AHI + offA + mt * 16 * SPITCH + kadd);
                ldm_x4(alo[mt][0], alo[mt][1], alo[mt][2], alo[mt][3],
                       base + OFF_ALO + offA + mt * 16 * SPITCH + kadd);
            }
            #pragma unroll
            for (int np = 0; np < 4; np++) {
                ldm_x4(bhi[2*np][0], bhi[2*np][1], bhi[2*np+1][0], bhi[2*np+1][1],
                       base + OFF_BHI + offB + np * 16 * SPITCH + kadd);
                ldm_x4(blo[2*np][0], blo[2*np][1], blo[2*np+1][0], blo[2*np+1][1],
                       base + OFF_BLO + offB + np * 16 * SPITCH + kadd);
            }
            #pragma unroll
            for (int mi = 0; mi < 2; mi++)
                #pragma unroll
                for (int ni = 0; ni < 8; ni++) {
                    mma_bf16(acc[mi][ni], ahi[mi], bhi[ni]);
                    mma_bf16(acc[mi][ni], ahi[mi], blo[ni]);
                    mma_bf16(acc[mi][ni], alo[mi], bhi[ni]);
                }
        }
        __syncthreads();
    }

    // ---- epilogue: direct global stores ----
    const int er = lane >> 2, ec = (lane & 3) * 2;
    #pragma unroll
    for (int mi = 0; mi < 2; mi++) {
        const int r_lo = m0 + warp_m * 32 + mi * 16 + er;
        #pragma unroll
        for (int ni = 0; ni < 8; ni++) {
            const int cc = n0 + warp_n * 64 + ni * 8 + ec;
            *(float2*)(C + (size_t)r_lo * Nc + cc)       = make_float2(acc[mi][ni][0], acc[mi][ni][1]);
            *(float2*)(C + (size_t)(r_lo + 8) * Nc + cc) = make_float2(acc[mi][ni][2], acc[mi][ni][3]);
        }
    }
}

// ==================== attention / aggregation kernels ====================
__global__ void s_kernel(const float* __restrict__ h, const float* __restrict__ a_s,
                         const float* __restrict__ a_d, int F) {
    int node = blockIdx.x * (blockDim.x >> 5) + (threadIdx.x >> 5);
    int lane = threadIdx.x & 31;
    if (node >= N_NODES) return;
    const float* hr = h + (size_t)node * F;
    float vs = 0.0f, vd = 0.0f;
    for (int f = lane; f < F; f += 32) {
        float x = hr[f];
        vs += x * a_s[f];
        vd += x * a_d[f];
    }
    #pragma unroll
    for (int o = 16; o > 0; o >>= 1) {
        vs += __shfl_down_sync(0xffffffffu, vs, o);
        vd += __shfl_down_sync(0xffffffffu, vd, o);
    }
    if (lane == 0) {
        g_ss[node] = vs;
        g_sd[node] = vd;
        g_m[node]  = -INFINITY;
        g_den[node] = 0.0f;
    }
}

__global__ void edge_max_kernel() {
    int e = blockIdx.x * blockDim.x + threadIdx.x;
    if (e >= NE) return;
    int s = g_src[e], d = g_dst[e];
    float v = g_ss[s] + g_sd[d];
    v = v > 0.0f ? v : 0.2f * v;
    g_ee[e] = v;
    atomicMaxF(&g_m[d], v);
}

__global__ void edge_exp_kernel() {
    int e = blockIdx.x * blockDim.x + threadIdx.x;
    if (e >= NE) return;
    int d = g_dst[e];
    float ee = __expf(g_ee[e] - g_m[d]);
    g_ee[e] = ee;
    atomicAdd(&g_den[d], ee);
}

__global__ void edge_agg_kernel(const float* __restrict__ h, float* __restrict__ out, int F) {
    int e = blockIdx.x * (blockDim.x >> 5) + (threadIdx.x >> 5);
    if (e >= NE) return;
    int lane = threadIdx.x & 31;
    int s = g_src[e], d = g_dst[e];
    float w = g_ee[e] / g_den[d];
    const float4* hs = (const float4*)(h + (size_t)s * F);
    float* o = out + (size_t)d * F;
    int F4 = F >> 2;
    for (int f = lane; f < F4; f += 32) {
        float4 v = hs[f];
        atomicAdd(o + f * 4 + 0, w * v.x);
        atomicAdd(o + f * 4 + 1, w * v.y);
        atomicAdd(o + f * 4 + 2, w * v.z);
        atomicAdd(o + f * 4 + 3, w * v.w);
    }
}

__global__ void bias_relu_kernel(float* __restrict__ p, const float* __restrict__ b,
                                 int F, int do_relu) {
    size_t i = (size_t)blockIdx.x * blockDim.x + threadIdx.x;
    size_t n = (size_t)N_NODES * F;
    if (i >= n) return;
    int f = (int)(i % F);
    float x = p[i] + b[f];
    p[i] = do_relu ? fmaxf(x, 0.0f) : x;
}

__global__ void gemm3_kernel(const float* __restrict__ A, const float* __restrict__ W,
                             float* __restrict__ C) {
    int i = blockIdx.x * blockDim.x + threadIdx.x;
    if (i >= N_NODES) return;
    const float* a = A + (size_t)i * H2;
    float acc[NC] = {0,0,0,0,0,0,0};
    for (int k = 0; k < H2; k++) {
        float av = a[k];
        const float* wr = W + k * NC;
        #pragma unroll
        for (int c = 0; c < NC; c++) acc[c] += av * wr[c];
    }
    #pragma unroll
    for (int c = 0; c < NC; c++) C[(size_t)i * NC + c] = acc[c];
}

__global__ void edge_agg7_kernel(const float* __restrict__ h, float* __restrict__ out) {
    int e = blockIdx.x * blockDim.x + threadIdx.x;
    if (e >= NE) return;
    int s = g_src[e], d = g_dst[e];
    float w = g_ee[e] / g_den[d];
    const float* hs = h + (size_t)s * NC;
    float* o = out + (size_t)d * NC;
    #pragma unroll
    for (int c = 0; c < NC; c++) atomicAdd(o + c, w * hs[c]);
}

__global__ void final_kernel(const float* __restrict__ agg, const float* __restrict__ b,
                             float* __restrict__ out) {
    int i = blockIdx.x * blockDim.x + threadIdx.x;
    if (i >= N_NODES) return;
    float z[NC];
    float mx = -INFINITY;
    #pragma unroll
    for (int c = 0; c < NC; c++) {
        z[c] = agg[(size_t)i * NC + c] + b[c];
        mx = fmaxf(mx, z[c]);
    }
    float ssum = 0.0f;
    #pragma unroll
    for (int c = 0; c < NC; c++) ssum += __expf(z[c] - mx);
    float l = logf(ssum);
    #pragma unroll
    for (int c = 0; c < NC; c++) out[(size_t)i * NC + c] = z[c] - mx - l;
}

// ==================== launcher ====================
extern "C" void kernel_launch(void* const* d_in, const int* in_sizes, int n_in,
                              void* d_out, int out_size) {
    const float* x   = (const float*)d_in[0];
    const void*  ei  = d_in[1];
    const float* W1  = (const float*)d_in[2];
    const float* as1 = (const float*)d_in[3];
    const float* ad1 = (const float*)d_in[4];
    const float* b1  = (const float*)d_in[5];
    const float* W2  = (const float*)d_in[6];
    const float* as2 = (const float*)d_in[7];
    const float* ad2 = (const float*)d_in[8];
    const float* b2  = (const float*)d_in[9];
    const float* W3  = (const float*)d_in[10];
    const float* as3 = (const float*)d_in[11];
    const float* ad3 = (const float*)d_in[12];
    const float* b3  = (const float*)d_in[13];
    float* out = (float*)d_out;

    float *buf1, *buf2, *cbuf;
    __nv_bfloat16 *ahi, *alo, *bhi, *blo;
    cudaGetSymbolAddress((void**)&buf1, g_buf1);
    cudaGetSymbolAddress((void**)&buf2, g_buf2);
    cudaGetSymbolAddress((void**)&cbuf, g_c);
    cudaGetSymbolAddress((void**)&ahi, g_Ahi);
    cudaGetSymbolAddress((void**)&alo, g_Alo);
    cudaGetSymbolAddress((void**)&bhi, g_Bhi);
    cudaGetSymbolAddress((void**)&blo, g_Blo);

    cudaFuncSetAttribute(gemm_tc_kernel, cudaFuncAttributeMaxDynamicSharedMemorySize, SMEM_DYN);

    const int BT = 256;
    const int edge_blocks      = (NE + BT - 1) / BT;
    const int edge_warp_blocks = (NE + (BT / 32) - 1) / (BT / 32);
    const int node_warp_blocks = (N_NODES + (BT / 32) - 1) / (BT / 32);
    const int node_blocks      = (N_NODES + BT - 1) / BT;

    detect_kernel<<<1, 128>>>((const unsigned int*)ei);
    prep_edges_kernel<<<edge_blocks, BT>>>(ei);

    // ---------------- layer 1: F_IN -> H1 ----------------
    split_A_kernel<<<4096, BT>>>(x, N_NODES, F_IN, K1PAD, ahi, alo);
    split_Wt_kernel<<<2048, BT>>>(W1, F_IN, H1, K1PAD, bhi, blo);
    gemm_tc_kernel<<<dim3(H1 / 128, MPAD / 128), BT, SMEM_DYN>>>(ahi, alo, bhi, blo, buf1, K1PAD, H1);
    s_kernel<<<node_warp_blocks, BT>>>(buf1, as1, ad1, H1);
    zero_kernel<<<2048, BT>>>(buf2, (size_t)N_NODES * H1);
    edge_max_kernel<<<edge_blocks, BT>>>();
    edge_exp_kernel<<<edge_blocks, BT>>>();
    edge_agg_kernel<<<edge_warp_blocks, BT>>>(buf1, buf2, H1);
    bias_relu_kernel<<<(int)(((size_t)N_NODES * H1 + BT - 1) / BT), BT>>>(buf2, b1, H1, 1);

    // ---------------- layer 2: H1 -> H2 ----------------
    split_A_kernel<<<4096, BT>>>(buf2, N_NODES, H1, H1, ahi, alo);
    split_Wt_kernel<<<2048, BT>>>(W2, H1, H2, H1, bhi, blo);
    gemm_tc_kernel<<<dim3(H2 / 128, MPAD / 128), BT, SMEM_DYN>>>(ahi, alo, bhi, blo, buf1, H1, H2);
    s_kernel<<<node_warp_blocks, BT>>>(buf1, as2, ad2, H2);
    zero_kernel<<<2048, BT>>>(buf2, (size_t)N_NODES * H2);
    edge_max_kernel<<<edge_blocks, BT>>>();
    edge_exp_kernel<<<edge_blocks, BT>>>();
    edge_agg_kernel<<<edge_warp_blocks, BT>>>(buf1, buf2, H2);
    bias_relu_kernel<<<(int)(((size_t)N_NODES * H2 + BT - 1) / BT), BT>>>(buf2, b2, H2, 1);

    // ---------------- layer 3: H2 -> NC ----------------
    gemm3_kernel<<<node_blocks, BT>>>(buf2, W3, buf1);
    s_kernel<<<node_warp_blocks, BT>>>(buf1, as3, ad3, NC);
    zero_kernel<<<512, BT>>>(cbuf, (size_t)N_NODES * NC);
    edge_max_kernel<<<edge_blocks, BT>>>();
    edge_exp_kernel<<<edge_blocks, BT>>>();
    edge_agg7_kernel<<<edge_blocks, BT>>>(buf1, cbuf);
    final_kernel<<<node_blocks, BT>>>(cbuf, b3, out);
}